// round 1
// baseline (speedup 1.0000x reference)
#include <cuda_runtime.h>
#include <cuda_bf16.h>
#include <cstdint>

// Problem constants
#define NB 128
#define HH 40
#define WW 40
#define HW 1600
#define NC 16
#define NS 32
#define NTHREADS 320
#define FRAME (NB*HW*NC)          // 3,276,800 floats per state frame
#define RGBFRAME (NB*HW*3)        // 614,400 rgb elements per frame
#define NFRAMES (NS+1)

// Fallback state buffers (only used if output has no stacked region)
__device__ float g_stA[FRAME];
__device__ float g_stB[FRAME];

// ---------------- packed f32x2 helpers ----------------
__device__ __forceinline__ unsigned long long pk2(float lo, float hi) {
    unsigned long long r;
    asm("mov.b64 %0, {%1, %2};" : "=l"(r) : "f"(lo), "f"(hi));
    return r;
}
__device__ __forceinline__ float2 upk2(unsigned long long v) {
    float2 r;
    asm("mov.b64 {%0, %1}, %2;" : "=f"(r.x), "=f"(r.y) : "l"(v));
    return r;
}
__device__ __forceinline__ unsigned long long fma2(unsigned long long a,
                                                   unsigned long long b,
                                                   unsigned long long c) {
    unsigned long long d;
    asm("fma.rn.f32x2 %0, %1, %2, %3;" : "=l"(d) : "l"(a), "l"(b), "l"(c));
    return d;
}

// ---------------- rgb emit ----------------
__device__ __forceinline__ void emit_rgb(unsigned char* rgb8, float* rgbf,
                                         int idx3, float r, float g, float b, float a) {
    float ac = fminf(fmaxf(a, 0.f), 1.f);
    float vr = fminf(fmaxf(1.f - ac + r, 0.f), 1.f) * 255.f;
    float vg = fminf(fmaxf(1.f - ac + g, 0.f), 1.f) * 255.f;
    float vb = fminf(fmaxf(1.f - ac + b, 0.f), 1.f) * 255.f;
    unsigned char ur = (unsigned char)vr;
    unsigned char ug = (unsigned char)vg;
    unsigned char ub = (unsigned char)vb;
    if (rgb8) { rgb8[idx3] = ur; rgb8[idx3+1] = ug; rgb8[idx3+2] = ub; }
    if (rgbf) { rgbf[idx3] = (float)ur; rgbf[idx3+1] = (float)ug; rgbf[idx3+2] = (float)ub; }
}

// ---------------- init: frame 0 copy + rgb0 ----------------
__global__ void nca_init(const float* __restrict__ src, float* __restrict__ dst,
                         unsigned char* rgb8, float* rgbf) {
    int idx = blockIdx.x * blockDim.x + threadIdx.x;   // pixel index over B*HW
    if (idx >= NB*HW) return;
    const float4* s4 = (const float4*)(src + (size_t)idx * NC);
    float4 a = s4[0], b = s4[1], c = s4[2], d = s4[3];
    float4* o4 = (float4*)(dst + (size_t)idx * NC);
    o4[0] = a; o4[1] = b; o4[2] = c; o4[3] = d;
    if (rgb8 || rgbf) emit_rgb(rgb8, rgbf, idx*3, a.x, a.y, a.z, a.w);
}

// Sobel tap tables (cross-correlation, /8 folded in)
__constant__ int   c_tdh[8] = {-1,-1,-1, 0, 0, 1, 1, 1};
__constant__ int   c_tdw[8] = {-1, 0, 1,-1, 1,-1, 0, 1};
__constant__ float c_twx[8] = {-0.125f, 0.f, 0.125f, -0.25f, 0.25f, -0.125f, 0.f, 0.125f};
__constant__ float c_twy[8] = {-0.125f, -0.25f, -0.125f, 0.f, 0.f, 0.125f, 0.25f, 0.125f};

// SMEM: S(SoA 25600) + AM(1600) + ALN(1600) + W1(6144) + b1(128) + W2p(2048)
#define SMEM_FLOATS (25600 + 1600 + 1600 + 6144 + 128 + 2048)
#define SMEM_BYTES  (SMEM_FLOATS * 4)

// ---------------- one NCA step, one CTA per batch image ----------------
__global__ void __launch_bounds__(NTHREADS, 1) nca_step(
    const float* __restrict__ in_state,    // [B,HW,16]
    float* __restrict__ out_state,         // [B,HW,16]
    const float* __restrict__ gW1,         // [128,48]
    const float* __restrict__ gb1,         // [128]
    const float* __restrict__ gW2,         // [16,128]
    const int*  __restrict__ gupd,         // [B,HW] (this step)
    unsigned char* rgb8,                   // frame pointer or null
    float* rgbf)                           // frame pointer or null
{
    extern __shared__ float sm[];
    float* S   = sm;               // [16][1600] SoA
    float* AM  = S + 25600;        // alive mask (old state)
    float* ALN = AM + 1600;        // new alpha (pre-mask)
    float* W1s = ALN + 1600;       // [128][48]
    float* B1s = W1s + 6144;       // [128]
    float* W2p = B1s + 128;        // [128][16]  (transposed W2)

    const int b   = blockIdx.x;
    const int tid = threadIdx.x;
    const float* gsrc = in_state + (size_t)b * HW * NC;
    float* gdst = out_state + (size_t)b * HW * NC;

    // load state -> SoA smem
    for (int i = tid; i < HW*NC/4; i += NTHREADS) {
        int pix = i >> 2, q = i & 3;
        float4 v = ((const float4*)gsrc)[i];
        int c0 = q * 4;
        S[(c0+0)*HW + pix] = v.x;
        S[(c0+1)*HW + pix] = v.y;
        S[(c0+2)*HW + pix] = v.z;
        S[(c0+3)*HW + pix] = v.w;
    }
    // weights
    for (int i = tid; i < 6144/4; i += NTHREADS)
        ((float4*)W1s)[i] = ((const float4*)gW1)[i];
    if (tid < 128) B1s[tid] = gb1[tid];
    for (int i = tid; i < 2048; i += NTHREADS) {
        int c = i >> 7, o = i & 127;
        W2p[o*16 + c] = gW2[i];
    }
    __syncthreads();

    // alive mask of old state: 3x3 max pool on alpha, >= 0.1
    {
        const float* AL = S + 3*HW;
        for (int pix = tid; pix < HW; pix += NTHREADS) {
            int h = pix / WW, w = pix % WW;
            float m = -1e30f;
            #pragma unroll
            for (int dh = -1; dh <= 1; dh++) {
                int nh = h + dh;
                if ((unsigned)nh >= (unsigned)HH) continue;
                #pragma unroll
                for (int dw = -1; dw <= 1; dw++) {
                    int nw = w + dw;
                    if ((unsigned)nw >= (unsigned)WW) continue;
                    m = fmaxf(m, AL[nh*WW + nw]);
                }
            }
            AM[pix] = (m >= 0.1f) ? 1.0f : 0.0f;
        }
    }
    __syncthreads();

    const int* updrow = gupd + b * HW;

    // phase 1: perception + MLP + update -> pre-mask new state
    #pragma unroll 1
    for (int k = 0; k < 5; k++) {
        int pix = k * NTHREADS + tid;
        int h = pix / WW, w = pix % WW;

        float p[48];
        float amc = AM[pix];
        #pragma unroll
        for (int c = 0; c < 16; c++) p[c] = S[c*HW + pix] * amc;
        #pragma unroll
        for (int c = 16; c < 48; c++) p[c] = 0.f;

        #pragma unroll
        for (int t = 0; t < 8; t++) {
            int nh = h + c_tdh[t], nw = w + c_tdw[t];
            if ((unsigned)nh < (unsigned)HH && (unsigned)nw < (unsigned)WW) {
                int n = nh * WW + nw;
                float amn = AM[n];
                float wx = c_twx[t], wy = c_twy[t];
                #pragma unroll
                for (int c = 0; c < 16; c++) {
                    float m = S[c*HW + n] * amn;
                    p[16 + c] += wx * m;
                    p[32 + c] += wy * m;
                }
            }
        }

        // pack perception into f32x2 pairs over i
        unsigned long long pp[24];
        #pragma unroll
        for (int i = 0; i < 24; i++) pp[i] = pk2(p[2*i], p[2*i+1]);

        unsigned long long upd2[8];
        #pragma unroll
        for (int i = 0; i < 8; i++) upd2[i] = pk2(0.f, 0.f);

        #pragma unroll 1
        for (int o = 0; o < 128; o++) {
            unsigned long long acc = pk2(B1s[o], 0.f);
            const unsigned long long* wr = (const unsigned long long*)(W1s + o*48);
            #pragma unroll
            for (int i = 0; i < 24; i++) acc = fma2(wr[i], pp[i], acc);
            float2 ah = upk2(acc);
            float hid = fmaxf(ah.x + ah.y, 0.f);
            unsigned long long hh = pk2(hid, hid);
            const unsigned long long* w2r = (const unsigned long long*)(W2p + o*16);
            #pragma unroll
            for (int cp = 0; cp < 8; cp++) upd2[cp] = fma2(w2r[cp], hh, upd2[cp]);
        }

        float um = (float)updrow[pix];
        float nv[16];
        #pragma unroll
        for (int cp = 0; cp < 8; cp++) {
            float2 u = upk2(upd2[cp]);
            nv[2*cp]   = S[(2*cp)*HW   + pix] + u.x * um;
            nv[2*cp+1] = S[(2*cp+1)*HW + pix] + u.y * um;
        }
        ALN[pix] = nv[3];
        float4* o4 = (float4*)(gdst + (size_t)pix * NC);
        o4[0] = make_float4(nv[0],  nv[1],  nv[2],  nv[3]);
        o4[1] = make_float4(nv[4],  nv[5],  nv[6],  nv[7]);
        o4[2] = make_float4(nv[8],  nv[9],  nv[10], nv[11]);
        o4[3] = make_float4(nv[12], nv[13], nv[14], nv[15]);
    }
    __syncthreads();

    // phase 2: alive mask on new state, apply in place, emit rgb
    #pragma unroll 1
    for (int k = 0; k < 5; k++) {
        int pix = k * NTHREADS + tid;
        int h = pix / WW, w = pix % WW;
        float m = -1e30f;
        #pragma unroll
        for (int dh = -1; dh <= 1; dh++) {
            int nh = h + dh;
            if ((unsigned)nh >= (unsigned)HH) continue;
            #pragma unroll
            for (int dw = -1; dw <= 1; dw++) {
                int nw = w + dw;
                if ((unsigned)nw >= (unsigned)WW) continue;
                m = fmaxf(m, ALN[nh*WW + nw]);
            }
        }
        float msk = (m >= 0.1f) ? 1.0f : 0.0f;

        float4* o4 = (float4*)(gdst + (size_t)pix * NC);
        float4 a = o4[0], bq = o4[1], cq = o4[2], dq = o4[3];
        a.x *= msk; a.y *= msk; a.z *= msk; a.w *= msk;
        bq.x *= msk; bq.y *= msk; bq.z *= msk; bq.w *= msk;
        cq.x *= msk; cq.y *= msk; cq.z *= msk; cq.w *= msk;
        dq.x *= msk; dq.y *= msk; dq.z *= msk; dq.w *= msk;
        o4[0] = a; o4[1] = bq; o4[2] = cq; o4[3] = dq;

        if (rgb8 || rgbf)
            emit_rgb(rgb8, rgbf, (b*HW + pix)*3, a.x, a.y, a.z, a.w);
    }
}

// ---------------- launch ----------------
extern "C" void kernel_launch(void* const* d_in, const int* in_sizes, int n_in,
                              void* d_out, int out_size) {
    const float* initial = (const float*)d_in[0];
    const float* W1 = (const float*)d_in[1];
    const float* b1 = (const float*)d_in[2];
    const float* W2 = (const float*)d_in[3];
    const int*  upd = (const int*)d_in[4];

    const long long NTOT = (long long)NFRAMES * NB * HW;     // 6,758,400
    const long long RGB_N = 3 * NTOT;                        // 20,275,200
    const long long STK_N = 16 * NTOT;                       // 108,134,400

    float* stacked = nullptr;
    unsigned char* rgb8 = nullptr;
    float* rgbf = nullptr;

    long long osz = (long long)out_size;
    if (osz >= RGB_N + 4*STK_N) {
        // raw byte concat: rgb uint8 then stacked f32
        rgb8 = (unsigned char*)d_out;
        stacked = (float*)((char*)d_out + RGB_N);
    } else if (osz >= RGB_N + STK_N) {
        // float concat: rgb (as floats) then stacked
        rgbf = (float*)d_out;
        stacked = (float*)d_out + RGB_N;
    } else if (osz >= STK_N) {
        stacked = (float*)d_out;
    } else if (osz >= RGB_N) {
        rgb8 = (unsigned char*)d_out;
    }

    // state frames: use stacked region if present, else fallback globals
    float* stA = nullptr;
    float* stB = nullptr;
    if (!stacked) {
        cudaGetSymbolAddress((void**)&stA, g_stA);
        cudaGetSymbolAddress((void**)&stB, g_stB);
    }

    cudaFuncSetAttribute(nca_step, cudaFuncAttributeMaxDynamicSharedMemorySize, SMEM_BYTES);

    float* frame0 = stacked ? stacked : stA;
    unsigned char* r8_0 = rgb8 ? rgb8 : nullptr;
    float* rf_0 = rgbf ? rgbf : nullptr;
    nca_init<<<(NB*HW + 255)/256, 256>>>(initial, frame0, r8_0, rf_0);

    for (int s = 0; s < NS; s++) {
        const float* src;
        float* dst;
        if (stacked) {
            src = stacked + (size_t)s * FRAME;
            dst = stacked + (size_t)(s+1) * FRAME;
        } else {
            src = (s & 1) ? stB : stA;
            dst = (s & 1) ? stA : stB;
        }
        unsigned char* r8 = rgb8 ? rgb8 + (size_t)(s+1) * RGBFRAME : nullptr;
        float* rf = rgbf ? rgbf + (size_t)(s+1) * RGBFRAME : nullptr;
        nca_step<<<NB, NTHREADS, SMEM_BYTES>>>(src, dst, W1, b1, W2,
                                               upd + (size_t)s * NB * HW, r8, rf);
    }
}

// round 3
// speedup vs baseline: 1.6152x; 1.6152x over previous
#include <cuda_runtime.h>
#include <cstdint>

#define NB 128
#define HH 40
#define WW 40
#define HW 1600
#define NC 16
#define NS 32
#define NTHREADS 320
#define FRAME (NB*HW*NC)
#define RGBFRAME (NB*HW*3)
#define NFRAMES (NS+1)

typedef unsigned long long u64;

__device__ float g_stA[FRAME];
__device__ float g_stB[FRAME];

// ---------------- packed f32x2 helpers ----------------
__device__ __forceinline__ u64 pk2(float lo, float hi) {
    u64 r; asm("mov.b64 %0, {%1, %2};" : "=l"(r) : "f"(lo), "f"(hi)); return r;
}
__device__ __forceinline__ float2 upk2(u64 v) {
    float2 r; asm("mov.b64 {%0, %1}, %2;" : "=f"(r.x), "=f"(r.y) : "l"(v)); return r;
}
__device__ __forceinline__ u64 fma2(u64 a, u64 b, u64 c) {
    u64 d; asm("fma.rn.f32x2 %0, %1, %2, %3;" : "=l"(d) : "l"(a), "l"(b), "l"(c)); return d;
}
__device__ __forceinline__ u64 mul2(u64 a, u64 b) {
    u64 d; asm("mul.rn.f32x2 %0, %1, %2;" : "=l"(d) : "l"(a), "l"(b)); return d;
}

// ---------------- explicit shared-memory access ----------------
__device__ __forceinline__ void lds_v2(uint32_t a, u64& x, u64& y) {
    asm volatile("ld.shared.v2.u64 {%0, %1}, [%2];" : "=l"(x), "=l"(y) : "r"(a));
}
__device__ __forceinline__ u64 lds_u64(uint32_t a) {
    u64 x; asm volatile("ld.shared.u64 %0, [%1];" : "=l"(x) : "r"(a)); return x;
}
__device__ __forceinline__ float lds_f32(uint32_t a) {
    float x; asm volatile("ld.shared.f32 %0, [%1];" : "=f"(x) : "r"(a)); return x;
}
__device__ __forceinline__ void sts_f32(uint32_t a, float v) {
    asm volatile("st.shared.f32 [%0], %1;" :: "r"(a), "f"(v));
}
__device__ __forceinline__ void sts_v4(uint32_t a, float4 v) {
    asm volatile("st.shared.v4.f32 [%0], {%1, %2, %3, %4};"
                 :: "r"(a), "f"(v.x), "f"(v.y), "f"(v.z), "f"(v.w));
}

// ---------------- rgb emit ----------------
__device__ __forceinline__ void emit_rgb(unsigned char* rgb8, float* rgbf,
                                         int idx3, float r, float g, float b, float a) {
    float ac = fminf(fmaxf(a, 0.f), 1.f);
    unsigned char ur = (unsigned char)(fminf(fmaxf(1.f - ac + r, 0.f), 1.f) * 255.f);
    unsigned char ug = (unsigned char)(fminf(fmaxf(1.f - ac + g, 0.f), 1.f) * 255.f);
    unsigned char ub = (unsigned char)(fminf(fmaxf(1.f - ac + b, 0.f), 1.f) * 255.f);
    if (rgb8) { rgb8[idx3] = ur; rgb8[idx3+1] = ug; rgb8[idx3+2] = ub; }
    if (rgbf) { rgbf[idx3] = (float)ur; rgbf[idx3+1] = (float)ug; rgbf[idx3+2] = (float)ub; }
}

// ---------------- init ----------------
__global__ void nca_init(const float* __restrict__ src, float* __restrict__ dst,
                         unsigned char* rgb8, float* rgbf) {
    int idx = blockIdx.x * blockDim.x + threadIdx.x;
    if (idx >= NB*HW) return;
    const float4* s4 = (const float4*)(src + (size_t)idx * NC);
    float4 a = s4[0], b = s4[1], c = s4[2], d = s4[3];
    float4* o4 = (float4*)(dst + (size_t)idx * NC);
    o4[0] = a; o4[1] = b; o4[2] = c; o4[3] = d;
    if (rgb8 || rgbf) emit_rgb(rgb8, rgbf, idx*3, a.x, a.y, a.z, a.w);
}

// SMEM byte offsets
#define SP_OFF   0          // state AoS, [1600] x 80B (16 floats + 4 pad)
#define AL_OFF   128000     // old alpha [1600]
#define AM_OFF   134400     // alive mask [1600]
#define ALN_OFF  140800     // new alpha [1600]
#define W1_OFF   147200     // [128][48]
#define W2_OFF   171776     // [128][16] transposed
#define B1_OFF   179968     // [128] u64 pairs (b1, 0)
#define CNT_OFF  180992     // int counter
#define LIST_OFF 181000     // u16[1600] active pixel list
#define SMEM_BYTES 184320

// ---------------- fused perception + MLP for PX active pixels ----------------
// Arithmetic is EXACTLY R1's per-pixel order:
//   acc = (b1,0); 24 sequential fma2 over pairs; hid = relu(acc.x + acc.y)
//   upd2[cp] += w2r[cp]*hid per o; writeback fma2(upd, 1, state)
template<int PX>
__device__ __forceinline__ void mlp_pixels(
    uint32_t smb, float* __restrict__ gdst, int pix0, int pix1)
{
    const float twx[8] = {-0.125f, 0.f, 0.125f, -0.25f, 0.25f, -0.125f, 0.f, 0.125f};
    const float twy[8] = {-0.125f, -0.25f, -0.125f, 0.f, 0.f, 0.125f, 0.25f, 0.125f};
    const int   tdh[8] = {-1,-1,-1, 0, 0, 1, 1, 1};
    const int   tdw[8] = {-1, 0, 1,-1, 1,-1, 0, 1};

    int pix[2]; pix[0] = pix0; pix[1] = pix1;

    // perception: pp[0..7]=masked, [8..15]=sx, [16..23]=sy (pairs of channels)
    u64 pp[PX][24];
    #pragma unroll
    for (int q = 0; q < PX; q++) {
        int p = pix[q];
        int h = p / WW, w = p % WW;
        float amc = lds_f32(smb + AM_OFF + p*4);
        u64 amc2 = pk2(amc, amc);
        uint32_t ra = smb + SP_OFF + p*80;
        #pragma unroll
        for (int j = 0; j < 4; j++) {
            u64 a, b; lds_v2(ra + j*16, a, b);
            pp[q][2*j]   = mul2(a, amc2);
            pp[q][2*j+1] = mul2(b, amc2);
        }
        #pragma unroll
        for (int j = 8; j < 24; j++) pp[q][j] = 0ull;

        #pragma unroll
        for (int t = 0; t < 8; t++) {
            int nh = h + tdh[t], nw = w + tdw[t];
            if ((unsigned)nh < (unsigned)HH && (unsigned)nw < (unsigned)WW) {
                int n = nh * WW + nw;
                float amn = lds_f32(smb + AM_OFF + n*4);
                u64 amn2 = pk2(amn, amn);
                u64 wx2 = pk2(twx[t], twx[t]);
                u64 wy2 = pk2(twy[t], twy[t]);
                uint32_t na = smb + SP_OFF + n*80;
                #pragma unroll
                for (int j = 0; j < 4; j++) {
                    u64 a, b; lds_v2(na + j*16, a, b);
                    u64 m0 = mul2(a, amn2), m1 = mul2(b, amn2);
                    pp[q][8+2*j]    = fma2(wx2, m0, pp[q][8+2*j]);
                    pp[q][8+2*j+1]  = fma2(wx2, m1, pp[q][8+2*j+1]);
                    pp[q][16+2*j]   = fma2(wy2, m0, pp[q][16+2*j]);
                    pp[q][16+2*j+1] = fma2(wy2, m1, pp[q][16+2*j+1]);
                }
            }
        }
    }

    u64 upd2[PX][8];
    #pragma unroll
    for (int q = 0; q < PX; q++)
        #pragma unroll
        for (int j = 0; j < 8; j++) upd2[q][j] = 0ull;

    #pragma unroll 1
    for (int o = 0; o < 128; o++) {
        uint32_t wa = smb + W1_OFF + o*192;
        u64 b1p = lds_u64(smb + B1_OFF + o*8);
        u64 acc[PX];
        #pragma unroll
        for (int q = 0; q < PX; q++) acc[q] = b1p;
        // single sequential chain per pixel — R1 order: pairs 0,1,2,...,23
        #pragma unroll
        for (int j = 0; j < 12; j++) {
            u64 w0, w1; lds_v2(wa + j*16, w0, w1);
            #pragma unroll
            for (int q = 0; q < PX; q++) {
                acc[q] = fma2(w0, pp[q][2*j],   acc[q]);
                acc[q] = fma2(w1, pp[q][2*j+1], acc[q]);
            }
        }
        u64 w2r[8];
        lds_v2(smb + W2_OFF + o*64,      w2r[0], w2r[1]);
        lds_v2(smb + W2_OFF + o*64 + 16, w2r[2], w2r[3]);
        lds_v2(smb + W2_OFF + o*64 + 32, w2r[4], w2r[5]);
        lds_v2(smb + W2_OFF + o*64 + 48, w2r[6], w2r[7]);
        #pragma unroll
        for (int q = 0; q < PX; q++) {
            float2 ah = upk2(acc[q]);
            float hid = fmaxf(ah.x + ah.y, 0.f);
            u64 h2 = pk2(hid, hid);
            #pragma unroll
            for (int cp = 0; cp < 8; cp++)
                upd2[q][cp] = fma2(w2r[cp], h2, upd2[q][cp]);
        }
    }

    // writeback (active pixels: mask == 1)
    u64 one2 = pk2(1.0f, 1.0f);
    #pragma unroll
    for (int q = 0; q < PX; q++) {
        int p = pix[q];
        uint32_t ra = smb + SP_OFF + p*80;
        float nv[16];
        #pragma unroll
        for (int j = 0; j < 4; j++) {
            u64 a, b; lds_v2(ra + j*16, a, b);
            u64 n0 = fma2(upd2[q][2*j],   one2, a);
            u64 n1 = fma2(upd2[q][2*j+1], one2, b);
            float2 f0 = upk2(n0), f1 = upk2(n1);
            nv[4*j] = f0.x; nv[4*j+1] = f0.y; nv[4*j+2] = f1.x; nv[4*j+3] = f1.y;
        }
        sts_f32(smb + ALN_OFF + p*4, nv[3]);
        float4* o4 = (float4*)(gdst + (size_t)p * NC);
        o4[0] = make_float4(nv[0],  nv[1],  nv[2],  nv[3]);
        o4[1] = make_float4(nv[4],  nv[5],  nv[6],  nv[7]);
        o4[2] = make_float4(nv[8],  nv[9],  nv[10], nv[11]);
        o4[3] = make_float4(nv[12], nv[13], nv[14], nv[15]);
    }
}

// ---------------- one NCA step, one CTA per batch image ----------------
__global__ void __launch_bounds__(NTHREADS, 1) nca_step(
    const float* __restrict__ in_state,
    float* __restrict__ out_state,
    const float* __restrict__ gW1,
    const float* __restrict__ gb1,
    const float* __restrict__ gW2,
    const int*  __restrict__ gupd,
    unsigned char* rgb8, float* rgbf)
{
    extern __shared__ float sm[];
    uint32_t smb;
    asm("{ .reg .u64 t; cvta.to.shared.u64 t, %1; cvt.u32.u64 %0, t; }"
        : "=r"(smb) : "l"(sm));
    int* cnt = (int*)((char*)sm + CNT_OFF);
    unsigned short* list = (unsigned short*)((char*)sm + LIST_OFF);

    const int b   = blockIdx.x;
    const int tid = threadIdx.x;
    const float* gsrc = in_state + (size_t)b * HW * NC;
    float* gdst = out_state + (size_t)b * HW * NC;

    if (tid == 0) cnt[0] = 0;

    // state -> padded AoS smem (+ alpha array)
    for (int i = tid; i < HW*NC/4; i += NTHREADS) {
        int pix = i >> 2, q = i & 3;
        float4 v = ((const float4*)gsrc)[i];
        sts_v4(smb + SP_OFF + pix*80 + q*16, v);
        if (q == 0) sts_f32(smb + AL_OFF + pix*4, v.w);
    }
    for (int i = tid; i < 6144/4; i += NTHREADS)
        sts_v4(smb + W1_OFF + i*16, ((const float4*)gW1)[i]);
    if (tid < 128) {
        sts_f32(smb + B1_OFF + tid*8,     gb1[tid]);
        sts_f32(smb + B1_OFF + tid*8 + 4, 0.f);
    }
    for (int i = tid; i < 2048; i += NTHREADS) {
        int c = i >> 7, o = i & 127;
        sts_f32(smb + W2_OFF + (o*16 + c)*4, gW2[i]);
    }
    __syncthreads();

    // alive mask of old state
    for (int pix = tid; pix < HW; pix += NTHREADS) {
        int h = pix / WW, w = pix % WW;
        float m = -1e30f;
        #pragma unroll
        for (int dh = -1; dh <= 1; dh++) {
            int nh = h + dh;
            if ((unsigned)nh >= (unsigned)HH) continue;
            #pragma unroll
            for (int dw = -1; dw <= 1; dw++) {
                int nw = w + dw;
                if ((unsigned)nw >= (unsigned)WW) continue;
                m = fmaxf(m, lds_f32(smb + AL_OFF + (nh*WW + nw)*4));
            }
        }
        sts_f32(smb + AM_OFF + pix*4, (m >= 0.1f) ? 1.0f : 0.0f);
    }
    __syncthreads();

    const int* updrow = gupd + b * HW;

    // compaction: collect active pixels; inactive = pure copy (bit-exact)
    {
        int myact[5], nact = 0;
        #pragma unroll
        for (int k = 0; k < 5; k++) {
            int p = k * NTHREADS + tid;
            if (updrow[p] != 0) {
                myact[nact++] = p;
            } else {
                uint32_t ra = smb + SP_OFF + p*80;
                float4* o4 = (float4*)(gdst + (size_t)p * NC);
                #pragma unroll
                for (int j = 0; j < 4; j++) {
                    u64 a, bb; lds_v2(ra + j*16, a, bb);
                    float2 f0 = upk2(a), f1 = upk2(bb);
                    o4[j] = make_float4(f0.x, f0.y, f1.x, f1.y);
                    if (j == 0) sts_f32(smb + ALN_OFF + p*4, f1.y);
                }
            }
        }
        int pos = atomicAdd(cnt, nact);
        for (int i = 0; i < nact; i++) list[pos + i] = (unsigned short)myact[i];
    }
    __syncthreads();

    // active pixels: fused perception + MLP, 2 per thread per pass
    {
        int A = cnt[0];
        for (int pi = tid; 2*pi < A; pi += NTHREADS) {
            int i0 = 2*pi, i1 = i0 + 1;
            if (i1 < A) {
                mlp_pixels<2>(smb, gdst, (int)list[i0], (int)list[i1]);
            } else {
                mlp_pixels<1>(smb, gdst, (int)list[i0], (int)list[i0]);
            }
        }
    }
    __syncthreads();

    // phase 2: alive mask on new state, apply, emit rgb
    #pragma unroll 1
    for (int k = 0; k < 5; k++) {
        int pix = k * NTHREADS + tid;
        int h = pix / WW, w = pix % WW;
        float m = -1e30f;
        #pragma unroll
        for (int dh = -1; dh <= 1; dh++) {
            int nh = h + dh;
            if ((unsigned)nh >= (unsigned)HH) continue;
            #pragma unroll
            for (int dw = -1; dw <= 1; dw++) {
                int nw = w + dw;
                if ((unsigned)nw >= (unsigned)WW) continue;
                m = fmaxf(m, lds_f32(smb + ALN_OFF + (nh*WW + nw)*4));
            }
        }
        float msk = (m >= 0.1f) ? 1.0f : 0.0f;

        float4* o4 = (float4*)(gdst + (size_t)pix * NC);
        float4 a = o4[0], bq = o4[1], cq = o4[2], dq = o4[3];
        a.x *= msk; a.y *= msk; a.z *= msk; a.w *= msk;
        bq.x *= msk; bq.y *= msk; bq.z *= msk; bq.w *= msk;
        cq.x *= msk; cq.y *= msk; cq.z *= msk; cq.w *= msk;
        dq.x *= msk; dq.y *= msk; dq.z *= msk; dq.w *= msk;
        o4[0] = a; o4[1] = bq; o4[2] = cq; o4[3] = dq;

        if (rgb8 || rgbf)
            emit_rgb(rgb8, rgbf, (b*HW + pix)*3, a.x, a.y, a.z, a.w);
    }
}

// ---------------- launch ----------------
extern "C" void kernel_launch(void* const* d_in, const int* in_sizes, int n_in,
                              void* d_out, int out_size) {
    const float* initial = (const float*)d_in[0];
    const float* W1 = (const float*)d_in[1];
    const float* b1 = (const float*)d_in[2];
    const float* W2 = (const float*)d_in[3];
    const int*  upd = (const int*)d_in[4];

    const long long NTOT = (long long)NFRAMES * NB * HW;
    const long long RGB_N = 3 * NTOT;
    const long long STK_N = 16 * NTOT;

    float* stacked = nullptr;
    unsigned char* rgb8 = nullptr;
    float* rgbf = nullptr;

    long long osz = (long long)out_size;
    if (osz >= RGB_N + 4*STK_N) {
        rgb8 = (unsigned char*)d_out;
        stacked = (float*)((char*)d_out + RGB_N);
    } else if (osz >= RGB_N + STK_N) {
        rgbf = (float*)d_out;
        stacked = (float*)d_out + RGB_N;
    } else if (osz >= STK_N) {
        stacked = (float*)d_out;
    } else if (osz >= RGB_N) {
        rgb8 = (unsigned char*)d_out;
    }

    float* stA = nullptr;
    float* stB = nullptr;
    if (!stacked) {
        cudaGetSymbolAddress((void**)&stA, g_stA);
        cudaGetSymbolAddress((void**)&stB, g_stB);
    }

    cudaFuncSetAttribute(nca_step, cudaFuncAttributeMaxDynamicSharedMemorySize, SMEM_BYTES);

    float* frame0 = stacked ? stacked : stA;
    nca_init<<<(NB*HW + 255)/256, 256>>>(initial, frame0, rgb8, rgbf);

    for (int s = 0; s < NS; s++) {
        const float* src;
        float* dst;
        if (stacked) {
            src = stacked + (size_t)s * FRAME;
            dst = stacked + (size_t)(s+1) * FRAME;
        } else {
            src = (s & 1) ? stB : stA;
            dst = (s & 1) ? stA : stB;
        }
        unsigned char* r8 = rgb8 ? rgb8 + (size_t)(s+1) * RGBFRAME : nullptr;
        float* rf = rgbf ? rgbf + (size_t)(s+1) * RGBFRAME : nullptr;
        nca_step<<<NB, NTHREADS, SMEM_BYTES>>>(src, dst, W1, b1, W2,
                                               upd + (size_t)s * NB * HW, r8, rf);
    }
}

// round 4
// speedup vs baseline: 1.6823x; 1.0416x over previous
#include <cuda_runtime.h>
#include <cstdint>

#define NB 128
#define HH 40
#define WW 40
#define HW 1600
#define NC 16
#define NS 32
#define NTHREADS 480
#define FRAME (NB*HW*NC)
#define RGBFRAME (NB*HW*3)
#define NFRAMES (NS+1)

typedef unsigned long long u64;

__device__ float g_stA[FRAME];
__device__ float g_stB[FRAME];

// ---------------- packed f32x2 helpers ----------------
__device__ __forceinline__ u64 pk2(float lo, float hi) {
    u64 r; asm("mov.b64 %0, {%1, %2};" : "=l"(r) : "f"(lo), "f"(hi)); return r;
}
__device__ __forceinline__ float2 upk2(u64 v) {
    float2 r; asm("mov.b64 {%0, %1}, %2;" : "=f"(r.x), "=f"(r.y) : "l"(v)); return r;
}
__device__ __forceinline__ u64 fma2(u64 a, u64 b, u64 c) {
    u64 d; asm("fma.rn.f32x2 %0, %1, %2, %3;" : "=l"(d) : "l"(a), "l"(b), "l"(c)); return d;
}
__device__ __forceinline__ u64 mul2(u64 a, u64 b) {
    u64 d; asm("mul.rn.f32x2 %0, %1, %2;" : "=l"(d) : "l"(a), "l"(b)); return d;
}

// ---------------- explicit shared-memory access ----------------
__device__ __forceinline__ void lds_v2(uint32_t a, u64& x, u64& y) {
    asm volatile("ld.shared.v2.u64 {%0, %1}, [%2];" : "=l"(x), "=l"(y) : "r"(a));
}
__device__ __forceinline__ float lds_f32(uint32_t a) {
    float x; asm volatile("ld.shared.f32 %0, [%1];" : "=f"(x) : "r"(a)); return x;
}
__device__ __forceinline__ void sts_f32(uint32_t a, float v) {
    asm volatile("st.shared.f32 [%0], %1;" :: "r"(a), "f"(v));
}
__device__ __forceinline__ void sts_v4(uint32_t a, float4 v) {
    asm volatile("st.shared.v4.f32 [%0], {%1, %2, %3, %4};"
                 :: "r"(a), "f"(v.x), "f"(v.y), "f"(v.z), "f"(v.w));
}

// ---------------- rgb emit ----------------
__device__ __forceinline__ void emit_rgb(unsigned char* rgb8, float* rgbf,
                                         int idx3, float r, float g, float b, float a) {
    float ac = fminf(fmaxf(a, 0.f), 1.f);
    unsigned char ur = (unsigned char)(fminf(fmaxf(1.f - ac + r, 0.f), 1.f) * 255.f);
    unsigned char ug = (unsigned char)(fminf(fmaxf(1.f - ac + g, 0.f), 1.f) * 255.f);
    unsigned char ub = (unsigned char)(fminf(fmaxf(1.f - ac + b, 0.f), 1.f) * 255.f);
    if (rgb8) { rgb8[idx3] = ur; rgb8[idx3+1] = ug; rgb8[idx3+2] = ub; }
    if (rgbf) { rgbf[idx3] = (float)ur; rgbf[idx3+1] = (float)ug; rgbf[idx3+2] = (float)ub; }
}

// ---------------- init ----------------
__global__ void nca_init(const float* __restrict__ src, float* __restrict__ dst,
                         unsigned char* rgb8, float* rgbf) {
    int idx = blockIdx.x * blockDim.x + threadIdx.x;
    if (idx >= NB*HW) return;
    const float4* s4 = (const float4*)(src + (size_t)idx * NC);
    float4 a = s4[0], b = s4[1], c = s4[2], d = s4[3];
    float4* o4 = (float4*)(dst + (size_t)idx * NC);
    o4[0] = a; o4[1] = b; o4[2] = c; o4[3] = d;
    if (rgb8 || rgbf) emit_rgb(rgb8, rgbf, idx*3, a.x, a.y, a.z, a.w);
}

// SMEM byte offsets
#define SP_OFF   0          // state AoS, [1600] x 80B (16 floats + 4 pad)
#define AL_OFF   128000     // old alpha [1600]
#define AM_OFF   134400     // alive mask [1600]
#define ALN_OFF  140800     // new alpha [1600]
#define W1_OFF   147200     // [128][48]
#define W2_OFF   171776     // [128][16] transposed
#define B1_OFF   179968     // [128] u64 pairs (b1, 0)
#define CNT_OFF  180992     // int counter
#define LIST_OFF 181000     // u16[1600] active pixel list
#define SMEM_BYTES 184320

// ---------------- fused perception + MLP for ONE active pixel ----------------
// Per-pixel arithmetic identical to R1/R3:
//   acc = (b1,0); 24 sequential fma2 over pairs 0..23; hid = relu(acc.x+acc.y)
//   upd2[cp] accumulated in o order 0..127. o-loop unrolled x2 with two
//   INDEPENDENT chains (different hidden units) — no re-association.
__device__ __forceinline__ void mlp_pixel(
    uint32_t smb, float* __restrict__ gdst, int p)
{
    const float twx[8] = {-0.125f, 0.f, 0.125f, -0.25f, 0.25f, -0.125f, 0.f, 0.125f};
    const float twy[8] = {-0.125f, -0.25f, -0.125f, 0.f, 0.f, 0.125f, 0.25f, 0.125f};
    const int   tdh[8] = {-1,-1,-1, 0, 0, 1, 1, 1};
    const int   tdw[8] = {-1, 0, 1,-1, 1,-1, 0, 1};

    int h = p / WW, w = p % WW;

    // perception: pp[0..7]=masked, [8..15]=sx, [16..23]=sy (pairs of channels)
    u64 pp[24];
    {
        float amc = lds_f32(smb + AM_OFF + p*4);
        u64 amc2 = pk2(amc, amc);
        uint32_t ra = smb + SP_OFF + p*80;
        #pragma unroll
        for (int j = 0; j < 4; j++) {
            u64 a, b; lds_v2(ra + j*16, a, b);
            pp[2*j]   = mul2(a, amc2);
            pp[2*j+1] = mul2(b, amc2);
        }
        #pragma unroll
        for (int j = 8; j < 24; j++) pp[j] = 0ull;

        #pragma unroll
        for (int t = 0; t < 8; t++) {
            int nh = h + tdh[t], nw = w + tdw[t];
            if ((unsigned)nh < (unsigned)HH && (unsigned)nw < (unsigned)WW) {
                int n = nh * WW + nw;
                float amn = lds_f32(smb + AM_OFF + n*4);
                u64 amn2 = pk2(amn, amn);
                u64 wx2 = pk2(twx[t], twx[t]);
                u64 wy2 = pk2(twy[t], twy[t]);
                uint32_t na = smb + SP_OFF + n*80;
                #pragma unroll
                for (int j = 0; j < 4; j++) {
                    u64 a, b; lds_v2(na + j*16, a, b);
                    u64 m0 = mul2(a, amn2), m1 = mul2(b, amn2);
                    pp[8+2*j]    = fma2(wx2, m0, pp[8+2*j]);
                    pp[8+2*j+1]  = fma2(wx2, m1, pp[8+2*j+1]);
                    pp[16+2*j]   = fma2(wy2, m0, pp[16+2*j]);
                    pp[16+2*j+1] = fma2(wy2, m1, pp[16+2*j+1]);
                }
            }
        }
    }

    u64 upd2[8];
    #pragma unroll
    for (int j = 0; j < 8; j++) upd2[j] = 0ull;

    #pragma unroll 1
    for (int o = 0; o < 128; o += 2) {
        uint32_t wa0 = smb + W1_OFF + o*192;
        uint32_t wa1 = wa0 + 192;
        u64 b1p0, b1p1;
        lds_v2(smb + B1_OFF + o*8, b1p0, b1p1);   // (b1[o],0),(b1[o+1],0)
        u64 acc0 = b1p0, acc1 = b1p1;
        #pragma unroll
        for (int j = 0; j < 12; j++) {
            u64 w0, w1; lds_v2(wa0 + j*16, w0, w1);
            acc0 = fma2(w0, pp[2*j],   acc0);
            acc0 = fma2(w1, pp[2*j+1], acc0);
            u64 v0, v1; lds_v2(wa1 + j*16, v0, v1);
            acc1 = fma2(v0, pp[2*j],   acc1);
            acc1 = fma2(v1, pp[2*j+1], acc1);
        }
        // W2 rows for o and o+1
        uint32_t w2a = smb + W2_OFF + o*64;
        u64 w2r[8];
        lds_v2(w2a,      w2r[0], w2r[1]);
        lds_v2(w2a + 16, w2r[2], w2r[3]);
        lds_v2(w2a + 32, w2r[4], w2r[5]);
        lds_v2(w2a + 48, w2r[6], w2r[7]);
        u64 w2s[8];
        lds_v2(w2a + 64, w2s[0], w2s[1]);
        lds_v2(w2a + 80, w2s[2], w2s[3]);
        lds_v2(w2a + 96, w2s[4], w2s[5]);
        lds_v2(w2a +112, w2s[6], w2s[7]);

        float2 a0 = upk2(acc0);
        float hid0 = fmaxf(a0.x + a0.y, 0.f);
        u64 h20 = pk2(hid0, hid0);
        #pragma unroll
        for (int cp = 0; cp < 8; cp++)
            upd2[cp] = fma2(w2r[cp], h20, upd2[cp]);

        float2 a1 = upk2(acc1);
        float hid1 = fmaxf(a1.x + a1.y, 0.f);
        u64 h21 = pk2(hid1, hid1);
        #pragma unroll
        for (int cp = 0; cp < 8; cp++)
            upd2[cp] = fma2(w2s[cp], h21, upd2[cp]);
    }

    // writeback (active pixel: mask == 1)
    u64 one2 = pk2(1.0f, 1.0f);
    uint32_t ra = smb + SP_OFF + p*80;
    float nv[16];
    #pragma unroll
    for (int j = 0; j < 4; j++) {
        u64 a, b; lds_v2(ra + j*16, a, b);
        u64 n0 = fma2(upd2[2*j],   one2, a);
        u64 n1 = fma2(upd2[2*j+1], one2, b);
        float2 f0 = upk2(n0), f1 = upk2(n1);
        nv[4*j] = f0.x; nv[4*j+1] = f0.y; nv[4*j+2] = f1.x; nv[4*j+3] = f1.y;
    }
    sts_f32(smb + ALN_OFF + p*4, nv[3]);
    float4* o4 = (float4*)(gdst + (size_t)p * NC);
    o4[0] = make_float4(nv[0],  nv[1],  nv[2],  nv[3]);
    o4[1] = make_float4(nv[4],  nv[5],  nv[6],  nv[7]);
    o4[2] = make_float4(nv[8],  nv[9],  nv[10], nv[11]);
    o4[3] = make_float4(nv[12], nv[13], nv[14], nv[15]);
}

// ---------------- one NCA step, one CTA per batch image ----------------
__global__ void __launch_bounds__(NTHREADS, 1) nca_step(
    const float* __restrict__ in_state,
    float* __restrict__ out_state,
    const float* __restrict__ gW1,
    const float* __restrict__ gb1,
    const float* __restrict__ gW2,
    const int*  __restrict__ gupd,
    unsigned char* rgb8, float* rgbf)
{
    extern __shared__ float sm[];
    uint32_t smb;
    asm("{ .reg .u64 t; cvta.to.shared.u64 t, %1; cvt.u32.u64 %0, t; }"
        : "=r"(smb) : "l"(sm));
    int* cnt = (int*)((char*)sm + CNT_OFF);
    unsigned short* list = (unsigned short*)((char*)sm + LIST_OFF);

    const int b   = blockIdx.x;
    const int tid = threadIdx.x;
    const float* gsrc = in_state + (size_t)b * HW * NC;
    float* gdst = out_state + (size_t)b * HW * NC;

    if (tid == 0) cnt[0] = 0;

    // state -> padded AoS smem (+ alpha array)
    for (int i = tid; i < HW*NC/4; i += NTHREADS) {
        int pix = i >> 2, q = i & 3;
        float4 v = ((const float4*)gsrc)[i];
        sts_v4(smb + SP_OFF + pix*80 + q*16, v);
        if (q == 0) sts_f32(smb + AL_OFF + pix*4, v.w);
    }
    for (int i = tid; i < 6144/4; i += NTHREADS)
        sts_v4(smb + W1_OFF + i*16, ((const float4*)gW1)[i]);
    if (tid < 128) {
        sts_f32(smb + B1_OFF + tid*8,     gb1[tid]);
        sts_f32(smb + B1_OFF + tid*8 + 4, 0.f);
    }
    for (int i = tid; i < 2048; i += NTHREADS) {
        int c = i >> 7, o = i & 127;
        sts_f32(smb + W2_OFF + (o*16 + c)*4, gW2[i]);
    }
    __syncthreads();

    // alive mask of old state
    for (int pix = tid; pix < HW; pix += NTHREADS) {
        int h = pix / WW, w = pix % WW;
        float m = -1e30f;
        #pragma unroll
        for (int dh = -1; dh <= 1; dh++) {
            int nh = h + dh;
            if ((unsigned)nh >= (unsigned)HH) continue;
            #pragma unroll
            for (int dw = -1; dw <= 1; dw++) {
                int nw = w + dw;
                if ((unsigned)nw >= (unsigned)WW) continue;
                m = fmaxf(m, lds_f32(smb + AL_OFF + (nh*WW + nw)*4));
            }
        }
        sts_f32(smb + AM_OFF + pix*4, (m >= 0.1f) ? 1.0f : 0.0f);
    }
    __syncthreads();

    const int* updrow = gupd + b * HW;

    // compaction: collect active pixels; inactive = pure copy (bit-exact)
    {
        int myact[4], nact = 0;
        for (int p = tid; p < HW; p += NTHREADS) {
            if (updrow[p] != 0) {
                myact[nact++] = p;
            } else {
                uint32_t ra = smb + SP_OFF + p*80;
                float4* o4 = (float4*)(gdst + (size_t)p * NC);
                #pragma unroll
                for (int j = 0; j < 4; j++) {
                    u64 a, bb; lds_v2(ra + j*16, a, bb);
                    float2 f0 = upk2(a), f1 = upk2(bb);
                    o4[j] = make_float4(f0.x, f0.y, f1.x, f1.y);
                    if (j == 0) sts_f32(smb + ALN_OFF + p*4, f1.y);
                }
            }
        }
        int pos = atomicAdd(cnt, nact);
        for (int i = 0; i < nact; i++) list[pos + i] = (unsigned short)myact[i];
    }
    __syncthreads();

    // active pixels: fused perception + MLP, strided
    {
        int A = cnt[0];
        for (int i = tid; i < A; i += NTHREADS)
            mlp_pixel(smb, gdst, (int)list[i]);
    }
    __syncthreads();

    // phase 2: alive mask on new state, apply, emit rgb
    for (int pix = tid; pix < HW; pix += NTHREADS) {
        int h = pix / WW, w = pix % WW;
        float m = -1e30f;
        #pragma unroll
        for (int dh = -1; dh <= 1; dh++) {
            int nh = h + dh;
            if ((unsigned)nh >= (unsigned)HH) continue;
            #pragma unroll
            for (int dw = -1; dw <= 1; dw++) {
                int nw = w + dw;
                if ((unsigned)nw >= (unsigned)WW) continue;
                m = fmaxf(m, lds_f32(smb + ALN_OFF + (nh*WW + nw)*4));
            }
        }
        float msk = (m >= 0.1f) ? 1.0f : 0.0f;

        float4* o4 = (float4*)(gdst + (size_t)pix * NC);
        float4 a = o4[0], bq = o4[1], cq = o4[2], dq = o4[3];
        a.x *= msk; a.y *= msk; a.z *= msk; a.w *= msk;
        bq.x *= msk; bq.y *= msk; bq.z *= msk; bq.w *= msk;
        cq.x *= msk; cq.y *= msk; cq.z *= msk; cq.w *= msk;
        dq.x *= msk; dq.y *= msk; dq.z *= msk; dq.w *= msk;
        o4[0] = a; o4[1] = bq; o4[2] = cq; o4[3] = dq;

        if (rgb8 || rgbf)
            emit_rgb(rgb8, rgbf, (b*HW + pix)*3, a.x, a.y, a.z, a.w);
    }
}

// ---------------- launch ----------------
extern "C" void kernel_launch(void* const* d_in, const int* in_sizes, int n_in,
                              void* d_out, int out_size) {
    const float* initial = (const float*)d_in[0];
    const float* W1 = (const float*)d_in[1];
    const float* b1 = (const float*)d_in[2];
    const float* W2 = (const float*)d_in[3];
    const int*  upd = (const int*)d_in[4];

    const long long NTOT = (long long)NFRAMES * NB * HW;
    const long long RGB_N = 3 * NTOT;
    const long long STK_N = 16 * NTOT;

    float* stacked = nullptr;
    unsigned char* rgb8 = nullptr;
    float* rgbf = nullptr;

    long long osz = (long long)out_size;
    if (osz >= RGB_N + 4*STK_N) {
        rgb8 = (unsigned char*)d_out;
        stacked = (float*)((char*)d_out + RGB_N);
    } else if (osz >= RGB_N + STK_N) {
        rgbf = (float*)d_out;
        stacked = (float*)d_out + RGB_N;
    } else if (osz >= STK_N) {
        stacked = (float*)d_out;
    } else if (osz >= RGB_N) {
        rgb8 = (unsigned char*)d_out;
    }

    float* stA = nullptr;
    float* stB = nullptr;
    if (!stacked) {
        cudaGetSymbolAddress((void**)&stA, g_stA);
        cudaGetSymbolAddress((void**)&stB, g_stB);
    }

    cudaFuncSetAttribute(nca_step, cudaFuncAttributeMaxDynamicSharedMemorySize, SMEM_BYTES);

    float* frame0 = stacked ? stacked : stA;
    nca_init<<<(NB*HW + 255)/256, 256>>>(initial, frame0, rgb8, rgbf);

    for (int s = 0; s < NS; s++) {
        const float* src;
        float* dst;
        if (stacked) {
            src = stacked + (size_t)s * FRAME;
            dst = stacked + (size_t)(s+1) * FRAME;
        } else {
            src = (s & 1) ? stB : stA;
            dst = (s & 1) ? stA : stB;
        }
        unsigned char* r8 = rgb8 ? rgb8 + (size_t)(s+1) * RGBFRAME : nullptr;
        float* rf = rgbf ? rgbf + (size_t)(s+1) * RGBFRAME : nullptr;
        nca_step<<<NB, NTHREADS, SMEM_BYTES>>>(src, dst, W1, b1, W2,
                                               upd + (size_t)s * NB * HW, r8, rf);
    }
}

// round 7
// speedup vs baseline: 1.9815x; 1.1778x over previous
#include <cuda_runtime.h>
#include <cstdint>

#define NB 128
#define HH 40
#define WW 40
#define HW 1600
#define NC 16
#define NS 32
#define NTHREADS 384
#define FRAME (NB*HW*NC)
#define RGBFRAME (NB*HW*3)
#define NFRAMES (NS+1)

typedef unsigned long long u64;

__device__ float g_stA[FRAME];
__device__ float g_stB[FRAME];

// ---------------- packed f32x2 helpers ----------------
__device__ __forceinline__ u64 pk2(float lo, float hi) {
    u64 r; asm("mov.b64 %0, {%1, %2};" : "=l"(r) : "f"(lo), "f"(hi)); return r;
}
__device__ __forceinline__ float2 upk2(u64 v) {
    float2 r; asm("mov.b64 {%0, %1}, %2;" : "=f"(r.x), "=f"(r.y) : "l"(v)); return r;
}
__device__ __forceinline__ u64 fma2(u64 a, u64 b, u64 c) {
    u64 d; asm("fma.rn.f32x2 %0, %1, %2, %3;" : "=l"(d) : "l"(a), "l"(b), "l"(c)); return d;
}
__device__ __forceinline__ u64 mul2(u64 a, u64 b) {
    u64 d; asm("mul.rn.f32x2 %0, %1, %2;" : "=l"(d) : "l"(a), "l"(b)); return d;
}

// ---------------- explicit shared-memory access ----------------
__device__ __forceinline__ void lds_v2(uint32_t a, u64& x, u64& y) {
    asm volatile("ld.shared.v2.u64 {%0, %1}, [%2];" : "=l"(x), "=l"(y) : "r"(a));
}
__device__ __forceinline__ u64 lds_u64(uint32_t a) {
    u64 x; asm volatile("ld.shared.u64 %0, [%1];" : "=l"(x) : "r"(a)); return x;
}
__device__ __forceinline__ float lds_f32(uint32_t a) {
    float x; asm volatile("ld.shared.f32 %0, [%1];" : "=f"(x) : "r"(a)); return x;
}
__device__ __forceinline__ float4 lds_v4f(uint32_t a) {
    float4 v;
    asm volatile("ld.shared.v4.f32 {%0, %1, %2, %3}, [%4];"
                 : "=f"(v.x), "=f"(v.y), "=f"(v.z), "=f"(v.w) : "r"(a));
    return v;
}
__device__ __forceinline__ void sts_f32(uint32_t a, float v) {
    asm volatile("st.shared.f32 [%0], %1;" :: "r"(a), "f"(v));
}
__device__ __forceinline__ void sts_v4(uint32_t a, float4 v) {
    asm volatile("st.shared.v4.f32 [%0], {%1, %2, %3, %4};"
                 :: "r"(a), "f"(v.x), "f"(v.y), "f"(v.z), "f"(v.w));
}

// ---------------- rgb emit ----------------
__device__ __forceinline__ void emit_rgb(unsigned char* rgb8, float* rgbf,
                                         int idx3, float r, float g, float b, float a) {
    float ac = fminf(fmaxf(a, 0.f), 1.f);
    unsigned char ur = (unsigned char)(fminf(fmaxf(1.f - ac + r, 0.f), 1.f) * 255.f);
    unsigned char ug = (unsigned char)(fminf(fmaxf(1.f - ac + g, 0.f), 1.f) * 255.f);
    unsigned char ub = (unsigned char)(fminf(fmaxf(1.f - ac + b, 0.f), 1.f) * 255.f);
    if (rgb8) { rgb8[idx3] = ur; rgb8[idx3+1] = ug; rgb8[idx3+2] = ub; }
    if (rgbf) { rgbf[idx3] = (float)ur; rgbf[idx3+1] = (float)ug; rgbf[idx3+2] = (float)ub; }
}

// ---------------- init ----------------
__global__ void nca_init(const float* __restrict__ src, float* __restrict__ dst,
                         unsigned char* rgb8, float* rgbf) {
    int idx = blockIdx.x * blockDim.x + threadIdx.x;
    if (idx >= NB*HW) return;
    const float4* s4 = (const float4*)(src + (size_t)idx * NC);
    float4 a = s4[0], b = s4[1], c = s4[2], d = s4[3];
    float4* o4 = (float4*)(dst + (size_t)idx * NC);
    o4[0] = a; o4[1] = b; o4[2] = c; o4[3] = d;
    if (rgb8 || rgbf) emit_rgb(rgb8, rgbf, idx*3, a.x, a.y, a.z, a.w);
}

// SMEM byte offsets
#define SP_OFF    0          // state AoS, [1600] x 80B (16 floats + 4 pad)
#define AL_OFF    128000     // old alpha [1600]
#define AM_OFF    134400     // alive mask [1600]
#define ALN_OFF   140800     // new alpha (pre-mask) [1600]
#define RGB4_OFF  147200     // new rgba (pre-mask) [1600] float4
#define W1_OFF    172800     // [128][48]
#define W2_OFF    197376     // [128][16] transposed
#define B1_OFF    205568     // [128] u64 pairs (b1, 0)
#define CNT_OFF   206592     // int counter
#define LIST_OFF  206600     // u16[1600] active pixel list
#define SMEM_BYTES 209920

// ---------------- fused perception + MLP for PX active pixels ----------------
// Per-pixel arithmetic EXACTLY R1/R3:
//   acc = (b1,0); 24 sequential fma2 over pairs 0..23; hid = relu(acc.x+acc.y)
//   upd2[cp] accumulated in o order 0..127; writeback fma2(upd, 1, state)
template<int PX>
__device__ __forceinline__ void mlp_pixels(
    uint32_t smb, float* __restrict__ gdst, int pix0, int pix1)
{
    const float twx[8] = {-0.125f, 0.f, 0.125f, -0.25f, 0.25f, -0.125f, 0.f, 0.125f};
    const float twy[8] = {-0.125f, -0.25f, -0.125f, 0.f, 0.f, 0.125f, 0.25f, 0.125f};
    const int   tdh[8] = {-1,-1,-1, 0, 0, 1, 1, 1};
    const int   tdw[8] = {-1, 0, 1,-1, 1,-1, 0, 1};

    int pix[2]; pix[0] = pix0; pix[1] = pix1;

    // perception: pp[0..7]=masked, [8..15]=sx, [16..23]=sy (pairs of channels)
    u64 pp[PX][24];
    #pragma unroll
    for (int q = 0; q < PX; q++) {
        int p = pix[q];
        int h = p / WW, w = p % WW;
        float amc = lds_f32(smb + AM_OFF + p*4);
        u64 amc2 = pk2(amc, amc);
        uint32_t ra = smb + SP_OFF + p*80;
        #pragma unroll
        for (int j = 0; j < 4; j++) {
            u64 a, b; lds_v2(ra + j*16, a, b);
            pp[q][2*j]   = mul2(a, amc2);
            pp[q][2*j+1] = mul2(b, amc2);
        }
        #pragma unroll
        for (int j = 8; j < 24; j++) pp[q][j] = 0ull;

        #pragma unroll
        for (int t = 0; t < 8; t++) {
            int nh = h + tdh[t], nw = w + tdw[t];
            if ((unsigned)nh < (unsigned)HH && (unsigned)nw < (unsigned)WW) {
                int n = nh * WW + nw;
                float amn = lds_f32(smb + AM_OFF + n*4);
                u64 amn2 = pk2(amn, amn);
                u64 wx2 = pk2(twx[t], twx[t]);
                u64 wy2 = pk2(twy[t], twy[t]);
                uint32_t na = smb + SP_OFF + n*80;
                #pragma unroll
                for (int j = 0; j < 4; j++) {
                    u64 a, b; lds_v2(na + j*16, a, b);
                    u64 m0 = mul2(a, amn2), m1 = mul2(b, amn2);
                    pp[q][8+2*j]    = fma2(wx2, m0, pp[q][8+2*j]);
                    pp[q][8+2*j+1]  = fma2(wx2, m1, pp[q][8+2*j+1]);
                    pp[q][16+2*j]   = fma2(wy2, m0, pp[q][16+2*j]);
                    pp[q][16+2*j+1] = fma2(wy2, m1, pp[q][16+2*j+1]);
                }
            }
        }
    }

    u64 upd2[PX][8];
    #pragma unroll
    for (int q = 0; q < PX; q++)
        #pragma unroll
        for (int j = 0; j < 8; j++) upd2[q][j] = 0ull;

    #pragma unroll 1
    for (int o = 0; o < 128; o++) {
        uint32_t wa = smb + W1_OFF + o*192;
        u64 b1p = lds_u64(smb + B1_OFF + o*8);
        u64 acc[PX];
        #pragma unroll
        for (int q = 0; q < PX; q++) acc[q] = b1p;
        // single sequential chain per pixel — R1 order: pairs 0..23
        #pragma unroll
        for (int j = 0; j < 12; j++) {
            u64 w0, w1; lds_v2(wa + j*16, w0, w1);
            #pragma unroll
            for (int q = 0; q < PX; q++) {
                acc[q] = fma2(w0, pp[q][2*j],   acc[q]);
                acc[q] = fma2(w1, pp[q][2*j+1], acc[q]);
            }
        }
        u64 w2r[8];
        lds_v2(smb + W2_OFF + o*64,      w2r[0], w2r[1]);
        lds_v2(smb + W2_OFF + o*64 + 16, w2r[2], w2r[3]);
        lds_v2(smb + W2_OFF + o*64 + 32, w2r[4], w2r[5]);
        lds_v2(smb + W2_OFF + o*64 + 48, w2r[6], w2r[7]);
        #pragma unroll
        for (int q = 0; q < PX; q++) {
            float2 ah = upk2(acc[q]);
            float hid = fmaxf(ah.x + ah.y, 0.f);
            u64 h2 = pk2(hid, hid);
            #pragma unroll
            for (int cp = 0; cp < 8; cp++)
                upd2[q][cp] = fma2(w2r[cp], h2, upd2[q][cp]);
        }
    }

    // writeback pre-mask state to gdst; stash alpha + rgba in smem
    u64 one2 = pk2(1.0f, 1.0f);
    #pragma unroll
    for (int q = 0; q < PX; q++) {
        int p = pix[q];
        uint32_t ra = smb + SP_OFF + p*80;
        float nv[16];
        #pragma unroll
        for (int j = 0; j < 4; j++) {
            u64 a, b; lds_v2(ra + j*16, a, b);
            u64 n0 = fma2(upd2[q][2*j],   one2, a);
            u64 n1 = fma2(upd2[q][2*j+1], one2, b);
            float2 f0 = upk2(n0), f1 = upk2(n1);
            nv[4*j] = f0.x; nv[4*j+1] = f0.y; nv[4*j+2] = f1.x; nv[4*j+3] = f1.y;
        }
        sts_f32(smb + ALN_OFF + p*4, nv[3]);
        sts_v4(smb + RGB4_OFF + p*16, make_float4(nv[0], nv[1], nv[2], nv[3]));
        float4* o4 = (float4*)(gdst + (size_t)p * NC);
        o4[0] = make_float4(nv[0],  nv[1],  nv[2],  nv[3]);
        o4[1] = make_float4(nv[4],  nv[5],  nv[6],  nv[7]);
        o4[2] = make_float4(nv[8],  nv[9],  nv[10], nv[11]);
        o4[3] = make_float4(nv[12], nv[13], nv[14], nv[15]);
    }
}

// ---------------- one NCA step, one CTA per batch image ----------------
__global__ void __launch_bounds__(NTHREADS, 1) nca_step(
    const float* __restrict__ in_state,
    float* __restrict__ out_state,
    const float* __restrict__ gW1,
    const float* __restrict__ gb1,
    const float* __restrict__ gW2,
    const int*  __restrict__ gupd,
    unsigned char* rgb8, float* rgbf)
{
    extern __shared__ float sm[];
    uint32_t smb;
    asm("{ .reg .u64 t; cvta.to.shared.u64 t, %1; cvt.u32.u64 %0, t; }"
        : "=r"(smb) : "l"(sm));
    int* cnt = (int*)((char*)sm + CNT_OFF);
    unsigned short* list = (unsigned short*)((char*)sm + LIST_OFF);

    const int b   = blockIdx.x;
    const int tid = threadIdx.x;
    const float* gsrc = in_state + (size_t)b * HW * NC;
    float* gdst = out_state + (size_t)b * HW * NC;

    if (tid == 0) cnt[0] = 0;

    // state -> padded AoS smem (+ alpha array)
    for (int i = tid; i < HW*NC/4; i += NTHREADS) {
        int pix = i >> 2, q = i & 3;
        float4 v = ((const float4*)gsrc)[i];
        sts_v4(smb + SP_OFF + pix*80 + q*16, v);
        if (q == 0) sts_f32(smb + AL_OFF + pix*4, v.w);
    }
    for (int i = tid; i < 6144/4; i += NTHREADS)
        sts_v4(smb + W1_OFF + i*16, ((const float4*)gW1)[i]);
    if (tid < 128) {
        sts_f32(smb + B1_OFF + tid*8,     gb1[tid]);
        sts_f32(smb + B1_OFF + tid*8 + 4, 0.f);
    }
    for (int i = tid; i < 2048; i += NTHREADS) {
        int c = i >> 7, o = i & 127;
        sts_f32(smb + W2_OFF + (o*16 + c)*4, gW2[i]);
    }
    __syncthreads();

    // alive mask of old state
    for (int pix = tid; pix < HW; pix += NTHREADS) {
        int h = pix / WW, w = pix % WW;
        float m = -1e30f;
        #pragma unroll
        for (int dh = -1; dh <= 1; dh++) {
            int nh = h + dh;
            if ((unsigned)nh >= (unsigned)HH) continue;
            #pragma unroll
            for (int dw = -1; dw <= 1; dw++) {
                int nw = w + dw;
                if ((unsigned)nw >= (unsigned)WW) continue;
                m = fmaxf(m, lds_f32(smb + AL_OFF + (nh*WW + nw)*4));
            }
        }
        sts_f32(smb + AM_OFF + pix*4, (m >= 0.1f) ? 1.0f : 0.0f);
    }
    __syncthreads();

    const int* updrow = gupd + b * HW;

    // compaction: collect active pixels; inactive = pure copy (bit-exact)
    {
        int myact[5], nact = 0;
        for (int p = tid; p < HW; p += NTHREADS) {
            if (updrow[p] != 0) {
                myact[nact++] = p;
            } else {
                uint32_t ra = smb + SP_OFF + p*80;
                float4* o4 = (float4*)(gdst + (size_t)p * NC);
                #pragma unroll
                for (int j = 0; j < 4; j++) {
                    u64 a, bb; lds_v2(ra + j*16, a, bb);
                    float2 f0 = upk2(a), f1 = upk2(bb);
                    o4[j] = make_float4(f0.x, f0.y, f1.x, f1.y);
                    if (j == 0) {
                        sts_f32(smb + ALN_OFF + p*4, f1.y);
                        sts_v4(smb + RGB4_OFF + p*16,
                               make_float4(f0.x, f0.y, f1.x, f1.y));
                    }
                }
            }
        }
        int pos = atomicAdd(cnt, nact);
        for (int i = 0; i < nact; i++) list[pos + i] = (unsigned short)myact[i];
    }
    __syncthreads();

    // active pixels: fused perception + MLP; pairs interleaved for balance
    {
        int A = cnt[0];
        #pragma unroll 1
        for (int base = 0; base < A; base += 2*NTHREADS) {
            int i0 = base + tid;
            int i1 = i0 + NTHREADS;
            if (i1 < A) {
                mlp_pixels<2>(smb, gdst, (int)list[i0], (int)list[i1]);
            } else if (i0 < A) {
                mlp_pixels<1>(smb, gdst, (int)list[i0], (int)list[i0]);
            }
        }
    }
    __syncthreads();

    // phase 2: alive mask on new state; only dead pixels get zero-writes
    for (int pix = tid; pix < HW; pix += NTHREADS) {
        int h = pix / WW, w = pix % WW;
        float m = -1e30f;
        #pragma unroll
        for (int dh = -1; dh <= 1; dh++) {
            int nh = h + dh;
            if ((unsigned)nh >= (unsigned)HH) continue;
            #pragma unroll
            for (int dw = -1; dw <= 1; dw++) {
                int nw = w + dw;
                if ((unsigned)nw >= (unsigned)WW) continue;
                m = fmaxf(m, lds_f32(smb + ALN_OFF + (nh*WW + nw)*4));
            }
        }
        float msk = (m >= 0.1f) ? 1.0f : 0.0f;

        if (msk == 0.0f) {
            float4 z = make_float4(0.f, 0.f, 0.f, 0.f);
            float4* o4 = (float4*)(gdst + (size_t)pix * NC);
            o4[0] = z; o4[1] = z; o4[2] = z; o4[3] = z;
        }
        if (rgb8 || rgbf) {
            float4 c = lds_v4f(smb + RGB4_OFF + pix*16);
            emit_rgb(rgb8, rgbf, (b*HW + pix)*3,
                     c.x*msk, c.y*msk, c.z*msk, c.w*msk);
        }
    }
}

// ---------------- launch ----------------
extern "C" void kernel_launch(void* const* d_in, const int* in_sizes, int n_in,
                              void* d_out, int out_size) {
    const float* initial = (const float*)d_in[0];
    const float* W1 = (const float*)d_in[1];
    const float* b1 = (const float*)d_in[2];
    const float* W2 = (const float*)d_in[3];
    const int*  upd = (const int*)d_in[4];

    const long long NTOT = (long long)NFRAMES * NB * HW;
    const long long RGB_N = 3 * NTOT;
    const long long STK_N = 16 * NTOT;

    float* stacked = nullptr;
    unsigned char* rgb8 = nullptr;
    float* rgbf = nullptr;

    long long osz = (long long)out_size;
    if (osz >= RGB_N + 4*STK_N) {
        rgb8 = (unsigned char*)d_out;
        stacked = (float*)((char*)d_out + RGB_N);
    } else if (osz >= RGB_N + STK_N) {
        rgbf = (float*)d_out;
        stacked = (float*)d_out + RGB_N;
    } else if (osz >= STK_N) {
        stacked = (float*)d_out;
    } else if (osz >= RGB_N) {
        rgb8 = (unsigned char*)d_out;
    }

    float* stA = nullptr;
    float* stB = nullptr;
    if (!stacked) {
        cudaGetSymbolAddress((void**)&stA, g_stA);
        cudaGetSymbolAddress((void**)&stB, g_stB);
    }

    cudaFuncSetAttribute(nca_step, cudaFuncAttributeMaxDynamicSharedMemorySize, SMEM_BYTES);

    float* frame0 = stacked ? stacked : stA;
    nca_init<<<(NB*HW + 255)/256, 256>>>(initial, frame0, rgb8, rgbf);

    for (int s = 0; s < NS; s++) {
        const float* src;
        float* dst;
        if (stacked) {
            src = stacked + (size_t)s * FRAME;
            dst = stacked + (size_t)(s+1) * FRAME;
        } else {
            src = (s & 1) ? stB : stA;
            dst = (s & 1) ? stA : stB;
        }
        unsigned char* r8 = rgb8 ? rgb8 + (size_t)(s+1) * RGBFRAME : nullptr;
        float* rf = rgbf ? rgbf + (size_t)(s+1) * RGBFRAME : nullptr;
        nca_step<<<NB, NTHREADS, SMEM_BYTES>>>(src, dst, W1, b1, W2,
                                               upd + (size_t)s * NB * HW, r8, rf);
    }
}